// round 7
// baseline (speedup 1.0000x reference)
#include <cuda_runtime.h>
#include <cuda_bf16.h>
#include <math.h>
#include <float.h>

// Problem constants
#define Bq   4
#define Tq   16
#define Sq   4096
#define Hq   32
#define KVq  8
#define Dq   128
#define DIMq 4096
#define HD   (Hq*Dq)          // 4096
#define KVD  (KVq*Dq)         // 1024
#define NTOT (HD + 2*KVD)     // 6144
#define M64  (Bq*Tq)          // 64
#define GQ   (Hq/KVq)         // 4
#define AROWS 64
#define NSPLIT 11
#define SCALE_F 0.08838834764831843f
#define SPLITK  4             // qkv
#define SPLITKO 8             // out proj

// ---------------- scratch ----------------------------------------------------
__device__ float g_qkvp[SPLITK][M64 * NTOT];
__device__ float g_outp[SPLITKO][M64 * DIMq];
__device__ float g_qatt[Bq*KVq*AROWS*Dq];
__device__ float g_knew[M64*KVq*Dq];
__device__ float g_vnew[M64*KVD];
__device__ float g_pacc[(size_t)NSPLIT*Bq*KVq*AROWS*Dq];
__device__ float g_pm  [NSPLIT*Bq*KVq*AROWS];
__device__ float g_pl  [NSPLIT*Bq*KVq*AROWS];
__device__ float g_y   [M64 * HD];

// ================= shared helpers ===========================================
__device__ __forceinline__ unsigned smem_u32(const void* p) {
    unsigned a;
    asm("{ .reg .u64 t; cvta.to.shared.u64 t, %1; cvt.u32.u64 %0, t; }"
        : "=r"(a) : "l"(p));
    return a;
}
__device__ __forceinline__ unsigned f2tf32(float x) {
    unsigned u; asm("cvt.rna.tf32.f32 %0, %1;" : "=r"(u) : "f"(x)); return u;
}
__device__ __forceinline__ void mma_tf32(float c[4], const unsigned a[4], const unsigned b[2]) {
    asm volatile(
        "mma.sync.aligned.m16n8k8.row.col.f32.tf32.tf32.f32 "
        "{%0,%1,%2,%3}, {%4,%5,%6,%7}, {%8,%9}, {%0,%1,%2,%3};\n"
        : "+f"(c[0]), "+f"(c[1]), "+f"(c[2]), "+f"(c[3])
        : "r"(a[0]), "r"(a[1]), "r"(a[2]), "r"(a[3]), "r"(b[0]), "r"(b[1]));
}
__device__ __forceinline__ void cpasync16(unsigned saddr, const float* g) {
    asm volatile("cp.async.ca.shared.global [%0], [%1], 16;" :: "r"(saddr), "l"(g));
}

// ================= tf32 split-K GEMM, 64x128 block tile =====================
#define BKg      32
#define GSTAGES  4
#define GSTRIDE  36
#define GSTG_FLT (192 * GSTRIDE)
#define GEMM_SMEM_BYTES (GSTAGES * GSTG_FLT * 4)
#define GK       4096

__device__ __forceinline__ void gemm_tile_mma(const float* __restrict__ A,
                                              const float* __restrict__ W,
                                              float* __restrict__ Cbase,
                                              int ldc, int kbeg, int nks) {
    extern __shared__ float smf[];
    const int tid  = threadIdx.x;
    const int lane = tid & 31;
    const int wid  = tid >> 5;
    const int gid  = lane >> 2;
    const int ctg  = lane & 3;
    const int wm   = wid & 1;
    const int wn   = wid >> 1;
    const int frA  = tid >> 2;
    const int fkA  = (tid & 3) * 8;
    const int frW  = tid >> 1;
    const int fkW  = (tid & 1) * 16;
    const unsigned sbase = smem_u32(smf);

    float acc[2][4][4];
#pragma unroll
    for (int mi = 0; mi < 2; mi++)
#pragma unroll
        for (int ni = 0; ni < 4; ni++)
#pragma unroll
            for (int j = 0; j < 4; j++) acc[mi][ni][j] = 0.f;

#pragma unroll
    for (int s = 0; s < GSTAGES - 1; s++) {
        unsigned sa = sbase + (unsigned)(s * GSTG_FLT + frA * GSTRIDE + fkA) * 4u;
        unsigned sw = sbase + (unsigned)(s * GSTG_FLT + (64 + frW) * GSTRIDE + fkW) * 4u;
        const float* ga = A + (size_t)frA * GK + kbeg + s * BKg + fkA;
        const float* gw = W + (size_t)frW * GK + kbeg + s * BKg + fkW;
        cpasync16(sa, ga);       cpasync16(sa + 16, ga + 4);
        cpasync16(sw, gw);       cpasync16(sw + 16, gw + 4);
        cpasync16(sw + 32, gw + 8); cpasync16(sw + 48, gw + 12);
        asm volatile("cp.async.commit_group;");
    }

    for (int i = 0; i < nks; i++) {
        asm volatile("cp.async.wait_group 2;");
        __syncthreads();
        const float* As = smf + (i & 3) * GSTG_FLT;
        const float* Ws = As + 64 * GSTRIDE;

#pragma unroll
        for (int ks = 0; ks < 4; ks++) {
            const int k = ks * 8;
            unsigned af[2][4], bf[4][2];
#pragma unroll
            for (int mi = 0; mi < 2; mi++) {
                int r = wm * 32 + mi * 16 + gid;
                af[mi][0] = f2tf32(As[r * GSTRIDE + k + ctg]);
                af[mi][1] = f2tf32(As[(r + 8) * GSTRIDE + k + ctg]);
                af[mi][2] = f2tf32(As[r * GSTRIDE + k + ctg + 4]);
                af[mi][3] = f2tf32(As[(r + 8) * GSTRIDE + k + ctg + 4]);
            }
#pragma unroll
            for (int ni = 0; ni < 4; ni++) {
                int n = wn * 32 + ni * 8 + gid;
                bf[ni][0] = f2tf32(Ws[n * GSTRIDE + k + ctg]);
                bf[ni][1] = f2tf32(Ws[n * GSTRIDE + k + ctg + 4]);
            }
#pragma unroll
            for (int mi = 0; mi < 2; mi++)
#pragma unroll
                for (int ni = 0; ni < 4; ni++)
                    mma_tf32(acc[mi][ni], af[mi], bf[ni]);
        }

        if (i + GSTAGES - 1 < nks) {
            int s = (i + 3) & 3;
            int k0 = kbeg + (i + 3) * BKg;
            unsigned sa = sbase + (unsigned)(s * GSTG_FLT + frA * GSTRIDE + fkA) * 4u;
            unsigned sw = sbase + (unsigned)(s * GSTG_FLT + (64 + frW) * GSTRIDE + fkW) * 4u;
            const float* ga = A + (size_t)frA * GK + k0 + fkA;
            const float* gw = W + (size_t)frW * GK + k0 + fkW;
            cpasync16(sa, ga);       cpasync16(sa + 16, ga + 4);
            cpasync16(sw, gw);       cpasync16(sw + 16, gw + 4);
            cpasync16(sw + 32, gw + 8); cpasync16(sw + 48, gw + 12);
            asm volatile("cp.async.commit_group;");
        } else {
            asm volatile("cp.async.commit_group;");
        }
    }

#pragma unroll
    for (int mi = 0; mi < 2; mi++)
#pragma unroll
        for (int ni = 0; ni < 4; ni++) {
            int r0 = wm * 32 + mi * 16 + gid;
            int c0 = wn * 32 + ni * 8 + 2 * ctg;
            *reinterpret_cast<float2*>(&Cbase[(size_t)r0 * ldc + c0]) =
                make_float2(acc[mi][ni][0], acc[mi][ni][1]);
            *reinterpret_cast<float2*>(&Cbase[(size_t)(r0 + 8) * ldc + c0]) =
                make_float2(acc[mi][ni][2], acc[mi][ni][3]);
        }
}

__global__ void qkv_kernel(const float* __restrict__ x,
                           const float* __restrict__ wq,
                           const float* __restrict__ wk,
                           const float* __restrict__ wv) {
    int n0 = blockIdx.x * 128;
    int sp = blockIdx.y;
    const float* W;
    if (n0 < HD)            W = wq + (size_t)n0 * DIMq;
    else if (n0 < HD + KVD) W = wk + (size_t)(n0 - HD) * DIMq;
    else                    W = wv + (size_t)(n0 - HD - KVD) * DIMq;
    gemm_tile_mma(x, W, g_qkvp[sp] + n0, NTOT, sp * (GK / SPLITK), GK / BKg / SPLITK);
}

__global__ void out_kernel(const float* __restrict__ wo) {
    int n0 = blockIdx.x * 128;
    int sp = blockIdx.y;
    gemm_tile_mma(g_y, wo + (size_t)n0 * DIMq, g_outp[sp] + n0, DIMq,
                  sp * (GK / SPLITKO), GK / BKg / SPLITKO);
}

__global__ void reduce_out_kernel(float* __restrict__ out) {
    int i = blockIdx.x * 256 + threadIdx.x;
    if (i >= M64 * DIMq / 4) return;
    float4 r = reinterpret_cast<const float4*>(g_outp[0])[i];
#pragma unroll
    for (int sp = 1; sp < SPLITKO; sp++) {
        float4 v = reinterpret_cast<const float4*>(g_outp[sp])[i];
        r.x += v.x; r.y += v.y; r.z += v.z; r.w += v.w;
    }
    reinterpret_cast<float4*>(out)[i] = r;
}

// ---------------- fused split-K reduce + RoPE -------------------------------
#define QPAIRS (M64*Hq*(Dq/2))   // 131072
#define KPAIRS (M64*KVq*(Dq/2))  // 32768
#define VQUADS (M64*KVD/4)       // 16384
__global__ void rope_fused_kernel(const float* __restrict__ fc,
                                  const float* __restrict__ fs) {
    int idx = blockIdx.x * blockDim.x + threadIdx.x;
    if (idx < QPAIRS) {
        int i = idx & 63;
        int h = (idx >> 6) & (Hq - 1);
        int m = idx >> 11;
        int t = m & (Tq - 1), b = m >> 4;
        size_t off = (size_t)m * NTOT + h * Dq + 2 * i;
        float x0 = 0.f, x1 = 0.f;
#pragma unroll
        for (int sp = 0; sp < SPLITK; sp++) {
            float2 p = *reinterpret_cast<const float2*>(&g_qkvp[sp][off]);
            x0 += p.x; x1 += p.y;
        }
        float c = fc[t * 64 + i], s = fs[t * 64 + i];
        int kv = h >> 2, hl = h & 3;
        float* q = g_qatt + ((((size_t)b * KVq + kv) * AROWS) + hl * Tq + t) * Dq + 2 * i;
        q[0] = (x0 * c - x1 * s) * SCALE_F;
        q[1] = (x0 * s + x1 * c) * SCALE_F;
    } else if (idx < QPAIRS + KPAIRS) {
        int j = idx - QPAIRS;
        int i = j & 63;
        int kv = (j >> 6) & (KVq - 1);
        int m = j >> 9;
        int t = m & (Tq - 1);
        size_t off = (size_t)m * NTOT + HD + kv * Dq + 2 * i;
        float x0 = 0.f, x1 = 0.f;
#pragma unroll
        for (int sp = 0; sp < SPLITK; sp++) {
            float2 p = *reinterpret_cast<const float2*>(&g_qkvp[sp][off]);
            x0 += p.x; x1 += p.y;
        }
        float c = fc[t * 64 + i], s = fs[t * 64 + i];
        float* k = g_knew + ((size_t)m * KVq + kv) * Dq + 2 * i;
        k[0] = x0 * c - x1 * s;
        k[1] = x0 * s + x1 * c;
    } else if (idx < QPAIRS + KPAIRS + VQUADS) {
        int j = idx - (QPAIRS + KPAIRS);
        int m = j >> 8;
        int c4 = (j & 255) * 4;
        size_t off = (size_t)m * NTOT + HD + KVD + c4;
        float4 r = make_float4(0.f, 0.f, 0.f, 0.f);
#pragma unroll
        for (int sp = 0; sp < SPLITK; sp++) {
            float4 v = *reinterpret_cast<const float4*>(&g_qkvp[sp][off]);
            r.x += v.x; r.y += v.y; r.z += v.z; r.w += v.w;
        }
        *reinterpret_cast<float4*>(&g_vnew[(size_t)m * KVD + c4]) = r;
    }
}

// ================= tensor-core flash attention v2 ===========================
// 64-key tiles, 3 barriers/tile, Q in registers, cp.async double-buffered K/V,
// warp-local partial softmax with shfl quad reductions.
// Warp grid: wq = wid&3 (16-row m-tile), kh = wid>>2 (32-key half / 64-col half).
#define KV_TILE 64
#define KS2 132
#define VS2 136
#define PS2 68
#define ATTN_SMEM_FLOATS (2*64*KS2 + 2*64*VS2 + 64*PS2 + 64 + 64 + 128 + 128)

__global__ void __launch_bounds__(256, 1)
attn_kernel(const float* __restrict__ k_cache,
            const float* __restrict__ v_cache,
            const int* __restrict__ input_pos) {
    extern __shared__ float sm[];
    float* Ks0  = sm;                       // [2][64][KS2] raw f32
    float* Vs0  = Ks0 + 2 * 64 * KS2;       // [2][64][VS2] raw f32
    float* Ps   = Vs0 + 2 * 64 * VS2;       // [64][PS2] tf32 bits
    float* rowm = Ps + 64 * PS2;
    float* rowl = rowm + 64;
    float* pmax = rowl + 64;                // [2][64]
    float* psum = pmax + 128;               // [2][64]
    unsigned* PsU = reinterpret_cast<unsigned*>(Ps);
    __shared__ int pos_s[Tq];

    const int tid  = threadIdx.x;
    const int lane = tid & 31;
    const int wid  = tid >> 5;
    const int gid  = lane >> 2;
    const int ctg  = lane & 3;
    const int wq   = wid & 3;
    const int kh   = wid >> 2;
    const int r0   = wq * 16 + gid;

    const int bk = blockIdx.x & 31;
    const int split = blockIdx.x >> 5;
    const int b = bk >> 3, kv = bk & 7;

    if (tid < Tq) pos_s[tid] = input_pos[tid];
    if (tid < AROWS) { rowm[tid] = -FLT_MAX; rowl[tid] = 0.f; }

    const int start_pos = __ldg(&input_pos[0]);
    const int limit = __ldg(&input_pos[Tq - 1]) + 1;
    const int ntiles = (limit + KV_TILE - 1) / KV_TILE;
    const int tpb = (ntiles + NSPLIT - 1) / NSPLIT;
    const int sbeg = split * tpb * KV_TILE;
    const int send = min(sbeg + tpb * KV_TILE, limit);

    // ---- Q into registers (tf32) ----
    unsigned qreg[16][4];
    {
        const float* q = g_qatt + ((size_t)b * KVq + kv) * AROWS * Dq;
        const float* qa = q + (size_t)r0 * Dq;
        const float* qb = q + (size_t)(r0 + 8) * Dq;
#pragma unroll
        for (int ks = 0; ks < 16; ks++) {
            qreg[ks][0] = f2tf32(qa[ks * 8 + ctg]);
            qreg[ks][1] = f2tf32(qb[ks * 8 + ctg]);
            qreg[ks][2] = f2tf32(qa[ks * 8 + ctg + 4]);
            qreg[ks][3] = f2tf32(qb[ks * 8 + ctg + 4]);
        }
    }

    const int prow = tid >> 5;           // 0..7
    const int pd4  = (tid & 31) * 4;
    const unsigned sb = smem_u32(sm);

    auto issue_tile = [&](int s0t, int buf) {
        unsigned kdst = sb + (unsigned)(buf * 64 * KS2) * 4u;
        unsigned vdst = sb + (unsigned)(2 * 64 * KS2 + buf * 64 * VS2) * 4u;
#pragma unroll
        for (int i = 0; i < 8; i++) {
            int row = prow + i * 8;
            int s = s0t + row;
            const float *ksrc, *vsrc;
            if (s >= start_pos && s < start_pos + Tq) {
                int mi = b * Tq + (s - start_pos);
                ksrc = &g_knew[((size_t)mi * KVq + kv) * Dq + pd4];
                vsrc = &g_vnew[(size_t)mi * KVD + kv * Dq + pd4];
            } else {
                size_t base = (((size_t)b * Sq + s) * KVq + kv) * Dq + pd4;
                ksrc = &k_cache[base];
                vsrc = &v_cache[base];
            }
            cpasync16(kdst + (unsigned)(row * KS2 + pd4) * 4u, ksrc);
            cpasync16(vdst + (unsigned)(row * VS2 + pd4) * 4u, vsrc);
        }
    };

    if (sbeg < send) issue_tile(sbeg, 0);
    asm volatile("cp.async.commit_group;");

    float acc[8][4];
#pragma unroll
    for (int nt = 0; nt < 8; nt++)
#pragma unroll
        for (int j = 0; j < 4; j++) acc[nt][j] = 0.f;

    const int pos0 = 2048 + gid;      // pos_s[gid] pattern; use smem after sync
    (void)pos0;

    int tl = 0;
    for (int s0 = sbeg; s0 < send; s0 += KV_TILE, tl++) {
        int buf = tl & 1;
        asm volatile("cp.async.wait_group 0;");
        __syncthreads();                         // sync1: tile ready, prev PV done
        if (s0 + KV_TILE < send) issue_tile(s0 + KV_TILE, buf ^ 1);
        asm volatile("cp.async.commit_group;");

        const float* Ksb = Ks0 + buf * 64 * KS2;
        const float* Vsb = Vs0 + buf * 64 * VS2;

        // ---- QK^T: warp = 16 rows x 32 keys ----
        float sc4[4][4];
#pragma unroll
        for (int nt = 0; nt < 4; nt++)
#pragma unroll
            for (int j = 0; j < 4; j++) sc4[nt][j] = 0.f;
#pragma unroll
        for (int ks = 0; ks < 16; ks++) {
            const int k = ks * 8;
#pragma unroll
            for (int nt = 0; nt < 4; nt++) {
                int n = kh * 32 + nt * 8 + gid;
                unsigned bfr[2];
                bfr[0] = f2tf32(Ksb[n * KS2 + k + ctg]);
                bfr[1] = f2tf32(Ksb[n * KS2 + k + ctg + 4]);
                mma_tf32(sc4[nt], qreg[ks], bfr);
            }
        }

        // ---- mask + warp-local partial max ----
        const int p0 = pos_s[gid];
        const int p1 = pos_s[gid + 8];
        float m0 = -FLT_MAX, m1 = -FLT_MAX;
#pragma unroll
        for (int nt = 0; nt < 4; nt++) {
            int cb = kh * 32 + nt * 8 + 2 * ctg;
            int sA = s0 + cb, sB = sA + 1;
            sc4[nt][0] = (sA < send && sA <= p0) ? sc4[nt][0] : -FLT_MAX;
            sc4[nt][1] = (sB < send && sB <= p0) ? sc4[nt][1] : -FLT_MAX;
            sc4[nt][2] = (sA < send && sA <= p1) ? sc4[nt][2] : -FLT_MAX;
            sc4[nt][3] = (sB < send && sB <= p1) ? sc4[nt][3] : -FLT_MAX;
            m0 = fmaxf(m0, fmaxf(sc4[nt][0], sc4[nt][1]));
            m1 = fmaxf(m1, fmaxf(sc4[nt][2], sc4[nt][3]));
        }
        m0 = fmaxf(m0, __shfl_xor_sync(0xFFFFFFFF, m0, 1));
        m0 = fmaxf(m0, __shfl_xor_sync(0xFFFFFFFF, m0, 2));
        m1 = fmaxf(m1, __shfl_xor_sync(0xFFFFFFFF, m1, 1));
        m1 = fmaxf(m1, __shfl_xor_sync(0xFFFFFFFF, m1, 2));
        if (ctg == 0) {
            pmax[kh * 64 + r0] = m0;
            pmax[kh * 64 + r0 + 8] = m1;
        }
        __syncthreads();                         // sync2: partial maxima ready

        // ---- joint max, exp, write P (tf32), partial sums ----
        float rm0 = rowm[r0], rm1 = rowm[r0 + 8];
        float mj0 = fmaxf(rm0, fmaxf(pmax[r0], pmax[64 + r0]));
        float mj1 = fmaxf(rm1, fmaxf(pmax[r0 + 8], pmax[64 + r0 + 8]));
        float scl0 = __expf(rm0 - mj0), scl1 = __expf(rm1 - mj1);
        float su0 = 0.f, su1 = 0.f;
#pragma unroll
        for (int nt = 0; nt < 4; nt++) {
            int cb = kh * 32 + nt * 8 + 2 * ctg;
            unsigned u0 = f2tf32(__expf(sc4[nt][0] - mj0));
            unsigned u1 = f2tf32(__expf(sc4[nt][1] - mj0));
            unsigned u2 = f2tf32(__expf(sc4[nt][2] - mj1));
            unsigned u3 = f2tf32(__expf(sc4[nt][3] - mj1));
            PsU[r0 * PS2 + cb]           = u0;
            PsU[r0 * PS2 + cb + 1]       = u1;
            PsU[(r0 + 8) * PS2 + cb]     = u2;
            PsU[(r0 + 8) * PS2 + cb + 1] = u3;
            su0 += __uint_as_float(u0) + __uint_as_float(u1);
            su1 += __uint_as_float(u2) + __uint_as_float(u3);
        }
        su0 += __shfl_xor_sync(0xFFFFFFFF, su0, 1);
        su0 += __shfl_xor_sync(0xFFFFFFFF, su0, 2);
        su1 += __shfl_xor_sync(0xFFFFFFFF, su1, 1);
        su1 += __shfl_xor_sync(0xFFFFFFFF, su1, 2);
        if (ctg == 0) {
            psum[kh * 64 + r0] = su0;
            psum[kh * 64 + r0 + 8] = su1;
        }
        __syncthreads();                         // sync3: P + partial sums ready

        // ---- stats update (uses OLD rowm; readers already hold copies) ----
        if (tid < AROWS) {
            float rmo = rowm[tid];
            float mj = fmaxf(rmo, fmaxf(pmax[tid], pmax[64 + tid]));
            rowl[tid] = rowl[tid] * __expf(rmo - mj) + psum[tid] + psum[64 + tid];
            rowm[tid] = mj;
        }

        // ---- rescale + P@V: warp = 16 rows x 64 d-cols ----
#pragma unroll
        for (int nt = 0; nt < 8; nt++) {
            acc[nt][0] *= scl0; acc[nt][1] *= scl0;
            acc[nt][2] *= scl1; acc[nt][3] *= scl1;
        }
#pragma unroll
        for (int ks = 0; ks < 8; ks++) {
            const int kk = ks * 8;
            unsigned a[4];
            a[0] = PsU[r0 * PS2 + kk + ctg];
            a[1] = PsU[(r0 + 8) * PS2 + kk + ctg];
            a[2] = PsU[r0 * PS2 + kk + ctg + 4];
            a[3] = PsU[(r0 + 8) * PS2 + kk + ctg + 4];
#pragma unroll
            for (int nt = 0; nt < 8; nt++) {
                int n = kh * 64 + nt * 8 + gid;
                unsigned bfr[2];
                bfr[0] = f2tf32(Vsb[(kk + ctg) * VS2 + n]);
                bfr[1] = f2tf32(Vsb[(kk + ctg + 4) * VS2 + n]);
                mma_tf32(acc[nt], a, bfr);
            }
        }
        // next iteration's sync1 protects the K/V buffers
    }

    __syncthreads();
    // ---- write split partials ----
    {
        float* pbase = g_pacc + ((size_t)split * Bq * KVq + bk) * AROWS * Dq;
#pragma unroll
        for (int nt = 0; nt < 8; nt++) {
            int col = kh * 64 + nt * 8 + 2 * ctg;
            *reinterpret_cast<float2*>(&pbase[(size_t)r0 * Dq + col]) =
                make_float2(acc[nt][0], acc[nt][1]);
            *reinterpret_cast<float2*>(&pbase[(size_t)(r0 + 8) * Dq + col]) =
                make_float2(acc[nt][2], acc[nt][3]);
        }
    }
    if (tid < AROWS) {
        int o = (split * Bq * KVq + bk) * AROWS + tid;
        g_pm[o] = rowm[tid];
        g_pl[o] = rowl[tid];
    }
}

// ---------------- combine splits --------------------------------------------
__global__ void combine_kernel() {
    int idx = blockIdx.x * 256 + threadIdx.x;
    if (idx >= Bq * KVq * AROWS * Dq) return;
    int d = idx & 127;
    int r = (idx >> 7) & 63;
    int bk = idx >> 13;
    float M = -FLT_MAX;
#pragma unroll
    for (int sp = 0; sp < NSPLIT; sp++)
        M = fmaxf(M, g_pm[(sp * Bq * KVq + bk) * AROWS + r]);
    float L = 0.f, Y = 0.f;
#pragma unroll
    for (int sp = 0; sp < NSPLIT; sp++) {
        int o = (sp * Bq * KVq + bk) * AROWS + r;
        float w = __expf(g_pm[o] - M);
        L += g_pl[o] * w;
        Y += g_pacc[(size_t)o * Dq + d] * w;
    }
    float y = Y / L;
    int b = bk >> 3, kv = bk & 7;
    int hl = r >> 4, t = r & 15;
    int h = kv * GQ + hl;
    int m = b * Tq + t;
    g_y[(size_t)m * HD + h * Dq + d] = y;
}

// ---------------- launch -----------------------------------------------------
extern "C" void kernel_launch(void* const* d_in, const int* in_sizes, int n_in,
                              void* d_out, int out_size) {
    const float* x  = (const float*)d_in[0];
    const float* fc = (const float*)d_in[1];
    const float* fs = (const float*)d_in[2];
    const int*  pos = (const int*)  d_in[3];
    const float* kc = (const float*)d_in[5];
    const float* vc = (const float*)d_in[6];
    const float* wq = (const float*)d_in[7];
    const float* wk = (const float*)d_in[8];
    const float* wv = (const float*)d_in[9];
    const float* wo = (const float*)d_in[10];
    float* out = (float*)d_out;

    cudaFuncSetAttribute(attn_kernel, cudaFuncAttributeMaxDynamicSharedMemorySize,
                         ATTN_SMEM_FLOATS * (int)sizeof(float));
    cudaFuncSetAttribute(qkv_kernel, cudaFuncAttributeMaxDynamicSharedMemorySize,
                         GEMM_SMEM_BYTES);
    cudaFuncSetAttribute(out_kernel, cudaFuncAttributeMaxDynamicSharedMemorySize,
                         GEMM_SMEM_BYTES);

    qkv_kernel<<<dim3(NTOT / 128, SPLITK), 256, GEMM_SMEM_BYTES>>>(x, wq, wk, wv);
    rope_fused_kernel<<<(QPAIRS + KPAIRS + VQUADS + 255) / 256, 256>>>(fc, fs);
    attn_kernel<<<NSPLIT * Bq * KVq, 256, ATTN_SMEM_FLOATS * sizeof(float)>>>(kc, vc, pos);
    combine_kernel<<<(Bq * KVq * AROWS * Dq + 255) / 256, 256>>>();
    out_kernel<<<dim3(DIMq / 128, SPLITKO), 256, GEMM_SMEM_BYTES>>>(wo);
    reduce_out_kernel<<<(M64 * DIMq / 4 + 255) / 256, 256>>>(out);
}